// round 2
// baseline (speedup 1.0000x reference)
#include <cuda_runtime.h>

#define BATCHES 8
#define N_PER 8192
#define M_PER 2048
#define C_FEAT 32
#define K 32
#define NCH (3 + C_FEAT)              // 35
#define THREADS 512
#define WARPS (THREADS / 32)          // 16
#define CTAS_PER_BATCH 32
#define Q_PER_CTA (M_PER / CTAS_PER_BATCH)   // 64
#define Q_PER_WARP (Q_PER_CTA / WARPS)       // 4
#define M_TOT (BATCHES * M_PER)              // 16384
#define FEAT_ELEMS ((size_t)M_TOT * NCH * K) // 18350080
#define SMEM_BYTES (3 * N_PER * 4 + WARPS * K * 4)  // 100352

__global__ __launch_bounds__(THREADS, 2)
void sqag_kernel(const float* __restrict__ xyz,
                 const float* __restrict__ new_xyz,
                 const float* __restrict__ features,
                 float* __restrict__ out)
{
    extern __shared__ float smem[];
    float* sx = smem;
    float* sy = smem + N_PER;
    float* sz = smem + 2 * N_PER;
    int*   slots = (int*)(smem + 3 * N_PER);

    const int batch = blockIdx.y;
    const int bbase = batch * N_PER;
    const float* bx = xyz + (size_t)bbase * 3;

    // Stage this batch's xyz into SMEM as SoA.
    for (int p = threadIdx.x; p < N_PER; p += THREADS) {
        const float* src = bx + 3 * p;
        sx[p] = src[0];
        sy[p] = src[1];
        sz[p] = src[2];
    }
    __syncthreads();

    const int wid  = threadIdx.x >> 5;
    const int lane = threadIdx.x & 31;
    int* ws = slots + wid * K;
    // JAX: d2(f32) < f32(0.04) -> 0.039999999105930328f (NOT 0.2f*0.2f)
    const float R2 = (float)(0.2 * 0.2);
    const unsigned lanemask_lt = (1u << lane) - 1u;

    for (int qi = 0; qi < Q_PER_WARP; qi++) {
        const int q_local = blockIdx.x * Q_PER_CTA + qi * WARPS + wid;
        const int m = batch * M_PER + q_local;
        const float* qp = new_xyz + (size_t)m * 3;
        const float qx = qp[0], qy = qp[1], qz = qp[2];

        int cnt = 0;  // warp-uniform
        for (int j0 = 0; j0 < N_PER && cnt < K; j0 += 32) {
            const int j = j0 + lane;
            const float dx = sx[j] - qx;
            const float dy = sy[j] - qy;
            const float dz = sz[j] - qz;
            // explicit rn mul/add: no FMA contraction, match XLA order
            const float d2 = __fadd_rn(__fadd_rn(__fmul_rn(dx, dx),
                                                 __fmul_rn(dy, dy)),
                                       __fmul_rn(dz, dz));
            const bool inb = d2 < R2;
            const unsigned mask = __ballot_sync(0xffffffffu, inb);
            if (inb) {
                const int pos = cnt + __popc(mask & lanemask_lt);
                if (pos < K) ws[pos] = j;
            }
            cnt += __popc(mask);
        }
        __syncwarp();

        const bool empty = (cnt == 0);
        const int c = cnt < K ? cnt : K;
        int i = 0;
        if (!empty) i = (lane < c) ? ws[lane] : ws[0];
        const float sc = empty ? 0.0f : 1.0f;

        const size_t ob = (size_t)m * (NCH * K);
        out[ob + 0 * K + lane] = (sx[i] - qx) * sc;
        out[ob + 1 * K + lane] = (sy[i] - qy) * sc;
        out[ob + 2 * K + lane] = (sz[i] - qz) * sc;

        const float4* fr = (const float4*)(features + (size_t)(bbase + i) * C_FEAT);
        #pragma unroll
        for (int t = 0; t < C_FEAT / 4; t++) {
            const float4 v = __ldg(fr + t);
            out[ob + (size_t)(3 + 4 * t + 0) * K + lane] = v.x * sc;
            out[ob + (size_t)(3 + 4 * t + 1) * K + lane] = v.y * sc;
            out[ob + (size_t)(3 + 4 * t + 2) * K + lane] = v.z * sc;
            out[ob + (size_t)(3 + 4 * t + 3) * K + lane] = v.w * sc;
        }

        // Output buffer dtype is float32: idx values must be stored as floats
        // (0..8191 are exactly representable).
        out[FEAT_ELEMS + (size_t)m * K + lane] = empty ? 0.0f : (float)i;
        __syncwarp();
    }
}

extern "C" void kernel_launch(void* const* d_in, const int* in_sizes, int n_in,
                              void* d_out, int out_size)
{
    const float* xyz      = (const float*)d_in[0];
    // d_in[1]: xyz_batch_cnt (constant N_PER, unused)
    const float* new_xyz  = (const float*)d_in[2];
    // d_in[3]: new_xyz_batch_cnt (constant M_PER, unused)
    const float* features = (const float*)d_in[4];

    cudaFuncSetAttribute(sqag_kernel,
                         cudaFuncAttributeMaxDynamicSharedMemorySize, SMEM_BYTES);

    dim3 grid(CTAS_PER_BATCH, BATCHES);
    sqag_kernel<<<grid, THREADS, SMEM_BYTES>>>(xyz, new_xyz, features, (float*)d_out);
}

// round 3
// speedup vs baseline: 1.2730x; 1.2730x over previous
#include <cuda_runtime.h>

#define BATCHES 8
#define N_PER 8192
#define M_PER 2048
#define C_FEAT 32
#define K 32
#define NCH (3 + C_FEAT)              // 35
#define THREADS 512
#define WARPS (THREADS / 32)          // 16
#define CHUNKS 37                     // 37*8 = 296 CTAs = exactly 2 per SM
#define Q_PER_CHUNK 56                // 37*56 = 2072 >= 2048
#define M_TOT (BATCHES * M_PER)              // 16384
#define FEAT_ELEMS ((size_t)M_TOT * NCH * K) // 18350080
// smem: float2 xy[8192] (64KB) + float z[8192] (32KB) + slots (2KB) + ctr
#define SMEM_BYTES (N_PER * 8 + N_PER * 4 + WARPS * K * 4 + 16)

__global__ __launch_bounds__(THREADS, 2)
void sqag_kernel(const float* __restrict__ xyz,
                 const float* __restrict__ new_xyz,
                 const float* __restrict__ features,
                 float* __restrict__ out)
{
    extern __shared__ float smem[];
    float2* sxy = (float2*)smem;                    // [N_PER]
    float*  sz  = smem + 2 * N_PER;                 // [N_PER]
    int*    slots = (int*)(smem + 3 * N_PER);       // [WARPS*K]
    int*    qctr  = slots + WARPS * K;

    const int batch = blockIdx.y;
    const int bbase = batch * N_PER;
    const float* bx = xyz + (size_t)bbase * 3;

    if (threadIdx.x == 0) *qctr = 0;

    // Stage this batch's xyz into SMEM (SoA: float2 xy + float z).
    for (int p = threadIdx.x; p < N_PER; p += THREADS) {
        const float* src = bx + 3 * p;
        sxy[p] = make_float2(src[0], src[1]);
        sz[p]  = src[2];
    }
    __syncthreads();

    const int wid  = threadIdx.x >> 5;
    const int lane = threadIdx.x & 31;
    int* ws = slots + wid * K;
    // JAX compares d2 < f32(0.04) = 0.039999999105930328f (NOT 0.2f*0.2f)
    const float R2 = (float)(0.2 * 0.2);
    const unsigned lanemask_lt = (1u << lane) - 1u;

    const int q_start = blockIdx.x * Q_PER_CHUNK;
    const int nq = min(Q_PER_CHUNK, M_PER - q_start);

    for (;;) {
        int qt;
        if (lane == 0) qt = atomicAdd(qctr, 1);
        qt = __shfl_sync(0xffffffffu, qt, 0);
        if (qt >= nq) break;

        const int m = batch * M_PER + q_start + qt;
        const float* qp = new_xyz + (size_t)m * 3;
        const float qx = qp[0], qy = qp[1], qz = qp[2];

        // ---- pipelined scan: 64 candidates per exit check, prefetch depth 64
        int cnt = 0;  // warp-uniform
        float2 a_xy = sxy[lane],      b_xy = sxy[32 + lane];
        float  a_z  = sz[lane],       b_z  = sz[32 + lane];
        for (int j0 = 0; j0 < N_PER && cnt < K; j0 += 64) {
            const int jn = j0 + 64;
            float2 c_xy, d_xy; float c_z, d_z;
            if (jn < N_PER) {
                c_xy = sxy[jn + lane]; d_xy = sxy[jn + 32 + lane];
                c_z  = sz[jn + lane];  d_z  = sz[jn + 32 + lane];
            }
            // block A
            {
                const float dx = a_xy.x - qx, dy = a_xy.y - qy, dz = a_z - qz;
                const float d2 = __fadd_rn(__fadd_rn(__fmul_rn(dx, dx),
                                                     __fmul_rn(dy, dy)),
                                           __fmul_rn(dz, dz));
                const bool inb = d2 < R2;
                const unsigned mask = __ballot_sync(0xffffffffu, inb);
                if (inb) {
                    const int pos = cnt + __popc(mask & lanemask_lt);
                    if (pos < K) ws[pos] = j0 + lane;
                }
                cnt += __popc(mask);
            }
            // block B
            {
                const float dx = b_xy.x - qx, dy = b_xy.y - qy, dz = b_z - qz;
                const float d2 = __fadd_rn(__fadd_rn(__fmul_rn(dx, dx),
                                                     __fmul_rn(dy, dy)),
                                           __fmul_rn(dz, dz));
                const bool inb = d2 < R2;
                const unsigned mask = __ballot_sync(0xffffffffu, inb);
                if (inb) {
                    const int pos = cnt + __popc(mask & lanemask_lt);
                    if (pos < K) ws[pos] = j0 + 32 + lane;
                }
                cnt += __popc(mask);
            }
            a_xy = c_xy; b_xy = d_xy; a_z = c_z; b_z = d_z;
        }
        __syncwarp();

        const bool empty = (cnt == 0);
        const int c = cnt < K ? cnt : K;
        int i = 0;
        if (!empty) i = (lane < c) ? ws[lane] : ws[0];
        const float sc = empty ? 0.0f : 1.0f;

        const float2 pxy = sxy[i];
        const float  pz  = sz[i];
        const size_t ob = (size_t)m * (NCH * K);
        out[ob + 0 * K + lane] = (pxy.x - qx) * sc;
        out[ob + 1 * K + lane] = (pxy.y - qy) * sc;
        out[ob + 2 * K + lane] = (pz    - qz) * sc;

        const float4* fr = (const float4*)(features + (size_t)(bbase + i) * C_FEAT);
        #pragma unroll
        for (int t = 0; t < C_FEAT / 4; t++) {
            const float4 v = __ldg(fr + t);
            out[ob + (size_t)(3 + 4 * t + 0) * K + lane] = v.x * sc;
            out[ob + (size_t)(3 + 4 * t + 1) * K + lane] = v.y * sc;
            out[ob + (size_t)(3 + 4 * t + 2) * K + lane] = v.z * sc;
            out[ob + (size_t)(3 + 4 * t + 3) * K + lane] = v.w * sc;
        }

        // Output dtype is float32: idx stored as float (0..8191 exact).
        out[FEAT_ELEMS + (size_t)m * K + lane] = empty ? 0.0f : (float)i;
        __syncwarp();
    }
}

extern "C" void kernel_launch(void* const* d_in, const int* in_sizes, int n_in,
                              void* d_out, int out_size)
{
    const float* xyz      = (const float*)d_in[0];
    // d_in[1]: xyz_batch_cnt (constant N_PER, unused)
    const float* new_xyz  = (const float*)d_in[2];
    // d_in[3]: new_xyz_batch_cnt (constant M_PER, unused)
    const float* features = (const float*)d_in[4];

    cudaFuncSetAttribute(sqag_kernel,
                         cudaFuncAttributeMaxDynamicSharedMemorySize, SMEM_BYTES);

    dim3 grid(CHUNKS, BATCHES);
    sqag_kernel<<<grid, THREADS, SMEM_BYTES>>>(xyz, new_xyz, features, (float*)d_out);
}